// round 1
// baseline (speedup 1.0000x reference)
#include <cuda_runtime.h>
#include <cuda_bf16.h>
#include <cstdint>

// Problem constants
#define BATCH 4
#define SEQ   4096
#define DIM   1024
#define NHEAD 16
#define HDIM  64
#define WIN   256
#define EXT   128
#define NGRP  (SEQ / WIN)          // 16
#define QKVDIM (3 * DIM)           // 3072
#define MROWS (BATCH * SEQ)        // 16384
#define ATT_SCALE 0.125f           // 64^-0.5

// ---------------- scratch (allocation-free: __device__ globals) ----------------
__device__ float g_qkv[(size_t)MROWS * QKVDIM];    // 192 MB: [b*4096+n][3072]
__device__ float g_attn[(size_t)MROWS * DIM];      // 64 MB
__device__ float g_wqkvT[(size_t)DIM * QKVDIM];    // 12 MB: [k][n]
__device__ float g_wprojT[(size_t)DIM * DIM];      // 4 MB

// ---------------- transpose: out[C][R] = in[R][C] ----------------
__global__ void k_transpose(const float* __restrict__ in, float* __restrict__ out,
                            int R, int C) {
    __shared__ float tile[32][33];
    int c = blockIdx.x * 32 + threadIdx.x;
    int r = blockIdx.y * 32 + threadIdx.y;
    #pragma unroll
    for (int i = 0; i < 32; i += 8)
        if (r + i < R && c < C) tile[threadIdx.y + i][threadIdx.x] = in[(size_t)(r + i) * C + c];
    __syncthreads();
    int c2 = blockIdx.y * 32 + threadIdx.x;   // index into R
    int r2 = blockIdx.x * 32 + threadIdx.y;   // index into C
    #pragma unroll
    for (int i = 0; i < 32; i += 8)
        if (r2 + i < C && c2 < R) out[(size_t)(r2 + i) * R + c2] = tile[threadIdx.x][threadIdx.y + i];
}

// ---------------- SGEMM: C[M][N] = A[M][K] * B[K][N] + bias[N] ----------------
// 128x128 block tile, K-step 8, 256 threads, 8x8 accumulators (strip-mined 4+4).
__global__ __launch_bounds__(256) void k_sgemm(const float* __restrict__ A,
                                               const float* __restrict__ B,
                                               const float* __restrict__ bias,
                                               float* __restrict__ C,
                                               int M, int N, int K) {
    __shared__ float As[8][128];
    __shared__ float Bs[8][128];
    const int tid = threadIdx.x;
    const int bm = blockIdx.y * 128;
    const int bn = blockIdx.x * 128;
    const int ar = tid >> 1;            // 0..127
    const int ac = (tid & 1) * 4;       // 0 or 4
    const int br = tid >> 5;            // 0..7
    const int bc = (tid & 31) * 4;      // 0..124
    const int tx = tid & 15;
    const int ty = tid >> 4;

    float acc[8][8];
    #pragma unroll
    for (int i = 0; i < 8; i++)
        #pragma unroll
        for (int j = 0; j < 8; j++) acc[i][j] = 0.f;

    for (int k0 = 0; k0 < K; k0 += 8) {
        float4 av = *(const float4*)&A[(size_t)(bm + ar) * K + k0 + ac];
        float4 bv = *(const float4*)&B[(size_t)(k0 + br) * N + bn + bc];
        As[ac + 0][ar] = av.x;
        As[ac + 1][ar] = av.y;
        As[ac + 2][ar] = av.z;
        As[ac + 3][ar] = av.w;
        *(float4*)&Bs[br][bc] = bv;
        __syncthreads();
        #pragma unroll
        for (int kk = 0; kk < 8; kk++) {
            float a[8], b[8];
            *(float4*)(a)     = *(float4*)&As[kk][ty * 4];
            *(float4*)(a + 4) = *(float4*)&As[kk][ty * 4 + 64];
            *(float4*)(b)     = *(float4*)&Bs[kk][tx * 4];
            *(float4*)(b + 4) = *(float4*)&Bs[kk][tx * 4 + 64];
            #pragma unroll
            for (int i = 0; i < 8; i++)
                #pragma unroll
                for (int j = 0; j < 8; j++)
                    acc[i][j] += a[i] * b[j];
        }
        __syncthreads();
    }

    #pragma unroll
    for (int i = 0; i < 8; i++) {
        int rl = (i < 4) ? (ty * 4 + i) : (64 + ty * 4 + i - 4);
        size_t rowoff = (size_t)(bm + rl) * N;
        #pragma unroll
        for (int j = 0; j < 8; j++) {
            int cl = (j < 4) ? (tx * 4 + j) : (64 + tx * 4 + j - 4);
            C[rowoff + bn + cl] = acc[i][j] + bias[bn + cl];
        }
    }
}

// ---------------- local attention ----------------
// grid (NGRP, NHEAD, BATCH), 256 threads; thread = one q row of the group.
// Online softmax over the 512-key window, 64-key smem chunks. Chunks are
// entirely valid or entirely invalid (g==0 skips c=0,1; g==15 skips c=6,7).
__global__ __launch_bounds__(256) void k_local_attn(const float* __restrict__ qkv,
                                                    float* __restrict__ attn) {
    __shared__ float Ks[64][64];
    __shared__ float Vs[64][64];
    const int g = blockIdx.x, h = blockIdx.y, b = blockIdx.z;
    const int tid = threadIdx.x;
    const int qn = g * WIN + tid;

    const float* qrow = qkv + ((size_t)b * SEQ + qn) * QKVDIM + h * HDIM;
    float q[HDIM];
    #pragma unroll
    for (int i = 0; i < 16; i++) *(float4*)&q[i * 4] = *(const float4*)&qrow[i * 4];

    float m = -1e30f, l = 0.f;
    float o[HDIM];
    #pragma unroll
    for (int d = 0; d < HDIM; d++) o[d] = 0.f;

    const int c0 = (g == 0) ? 2 : 0;
    const int c1 = (g == NGRP - 1) ? 6 : 8;

    for (int c = c0; c < c1; c++) {
        const int base = g * WIN - EXT + c * 64;
        __syncthreads();
        // load 64x64 K and V tiles (each thread: 4 float4 per tile)
        #pragma unroll
        for (int i = 0; i < 4; i++) {
            int idx = tid * 4 + i;
            int row = idx >> 4;
            int col = (idx & 15) * 4;
            const float* kp = qkv + ((size_t)b * SEQ + base + row) * QKVDIM + DIM + h * HDIM + col;
            *(float4*)&Ks[row][col] = *(const float4*)kp;
            *(float4*)&Vs[row][col] = *(const float4*)(kp + DIM);
        }
        __syncthreads();

        for (int kk = 0; kk < 64; kk++) {
            float s0 = 0.f, s1 = 0.f, s2 = 0.f, s3 = 0.f;
            #pragma unroll
            for (int d4 = 0; d4 < 16; d4++) {
                float4 kv = *(float4*)&Ks[kk][d4 * 4];
                s0 += q[d4 * 4 + 0] * kv.x;
                s1 += q[d4 * 4 + 1] * kv.y;
                s2 += q[d4 * 4 + 2] * kv.z;
                s3 += q[d4 * 4 + 3] * kv.w;
            }
            float s = ((s0 + s1) + (s2 + s3)) * ATT_SCALE;
            if (s > m) {
                float corr = __expf(m - s);
                l *= corr;
                #pragma unroll
                for (int d = 0; d < HDIM; d++) o[d] *= corr;
                m = s;
            }
            float p = __expf(s - m);
            l += p;
            #pragma unroll
            for (int d4 = 0; d4 < 16; d4++) {
                float4 vv = *(float4*)&Vs[kk][d4 * 4];
                o[d4 * 4 + 0] += p * vv.x;
                o[d4 * 4 + 1] += p * vv.y;
                o[d4 * 4 + 2] += p * vv.z;
                o[d4 * 4 + 3] += p * vv.w;
            }
        }
    }

    const float inv = 1.f / l;
    float* op = attn + ((size_t)b * SEQ + qn) * DIM + h * HDIM;
    #pragma unroll
    for (int i = 0; i < 16; i++) {
        float4 v;
        v.x = o[i * 4 + 0] * inv;
        v.y = o[i * 4 + 1] * inv;
        v.z = o[i * 4 + 2] * inv;
        v.w = o[i * 4 + 3] * inv;
        *(float4*)&op[i * 4] = v;
    }
}

// ---------------- launch ----------------
extern "C" void kernel_launch(void* const* d_in, const int* in_sizes, int n_in,
                              void* d_out, int out_size) {
    const float* x      = (const float*)d_in[0];   // [4,4096,1024]
    const float* w_qkv  = (const float*)d_in[1];   // [3072,1024]
    const float* b_qkv  = (const float*)d_in[2];   // [3072]
    const float* w_proj = (const float*)d_in[3];   // [1024,1024]
    const float* b_proj = (const float*)d_in[4];   // [1024]
    float* out = (float*)d_out;                    // [4,4096,1024]

    float *qkv, *attn, *wqkvT, *wprojT;
    cudaGetSymbolAddress((void**)&qkv,    g_qkv);
    cudaGetSymbolAddress((void**)&attn,   g_attn);
    cudaGetSymbolAddress((void**)&wqkvT,  g_wqkvT);
    cudaGetSymbolAddress((void**)&wprojT, g_wprojT);

    // 1. transpose weights: wT[k][n] = w[n][k]
    {
        dim3 t(32, 8);
        k_transpose<<<dim3(DIM / 32, QKVDIM / 32), t>>>(w_qkv, wqkvT, QKVDIM, DIM);
        k_transpose<<<dim3(DIM / 32, DIM / 32), t>>>(w_proj, wprojT, DIM, DIM);
    }

    // 2. QKV projection: g_qkv[16384][3072] = x[16384][1024] * wqkvT[1024][3072] + b_qkv
    k_sgemm<<<dim3(QKVDIM / 128, MROWS / 128), 256>>>(x, wqkvT, b_qkv, qkv,
                                                      MROWS, QKVDIM, DIM);

    // 3. local windowed attention -> g_attn[16384][1024]
    k_local_attn<<<dim3(NGRP, NHEAD, BATCH), 256>>>(qkv, attn);

    // 4. output projection: out = g_attn * wprojT + b_proj
    k_sgemm<<<dim3(DIM / 128, MROWS / 128), 256>>>(attn, wprojT, b_proj, out,
                                                   MROWS, DIM, DIM);
}

// round 5
// speedup vs baseline: 1.6747x; 1.6747x over previous
#include <cuda_runtime.h>
#include <cuda_bf16.h>
#include <cstdint>

// Problem constants
#define BATCH 4
#define SEQ   4096
#define DIM   1024
#define NHEAD 16
#define HDIM  64
#define WIN   256
#define EXT   128
#define NGRP  (SEQ / WIN)          // 16
#define QKVDIM (3 * DIM)           // 3072
#define MROWS (BATCH * SEQ)        // 16384
#define ATT_SCALE 0.125f           // 64^-0.5

// ---------------- scratch (allocation-free: __device__ globals) ----------------
__device__ float g_qkv[(size_t)MROWS * QKVDIM];            // 192 MB fp32
__device__ float g_attn[(size_t)MROWS * DIM];              // 64 MB fp32
__device__ __nv_bfloat16 g_x_hi[(size_t)MROWS * DIM];      // 32 MB
__device__ __nv_bfloat16 g_x_lo[(size_t)MROWS * DIM];
__device__ __nv_bfloat16 g_wqkv_hi[(size_t)QKVDIM * DIM];  // 6 MB
__device__ __nv_bfloat16 g_wqkv_lo[(size_t)QKVDIM * DIM];
__device__ __nv_bfloat16 g_attn_hi[(size_t)MROWS * DIM];
__device__ __nv_bfloat16 g_attn_lo[(size_t)MROWS * DIM];
__device__ __nv_bfloat16 g_wproj_hi[(size_t)DIM * DIM];    // 2 MB
__device__ __nv_bfloat16 g_wproj_lo[(size_t)DIM * DIM];

// ================= PTX helpers (base sm_103: NO 'a'-gated instructions) =================
__device__ __forceinline__ uint32_t smem_u32(const void* p) {
    uint32_t a;
    asm("{ .reg .u64 t; cvta.to.shared.u64 t, %1; cvt.u32.u64 %0, t; }" : "=r"(a) : "l"(p));
    return a;
}
#define CP_ASYNC16(s, g) \
    asm volatile("cp.async.cg.shared.global [%0], [%1], 16;" :: "r"(s), "l"(g))
#define CP_COMMIT() asm volatile("cp.async.commit_group;" ::: "memory")
#define CP_WAIT1()  asm volatile("cp.async.wait_group 1;" ::: "memory")

__device__ __forceinline__ void ldm_x4(uint32_t* r, uint32_t a) {
    asm volatile("ldmatrix.sync.aligned.m8n8.x4.shared.b16 {%0,%1,%2,%3}, [%4];"
                 : "=r"(r[0]), "=r"(r[1]), "=r"(r[2]), "=r"(r[3]) : "r"(a));
}
__device__ __forceinline__ void ldm_x2(uint32_t* r, uint32_t a) {
    asm volatile("ldmatrix.sync.aligned.m8n8.x2.shared.b16 {%0,%1}, [%2];"
                 : "=r"(r[0]), "=r"(r[1]) : "r"(a));
}
__device__ __forceinline__ void mma_bf16(float* d, const uint32_t* a, const uint32_t* b) {
    asm volatile("mma.sync.aligned.m16n8k16.row.col.f32.bf16.bf16.f32 "
                 "{%0,%1,%2,%3}, {%4,%5,%6,%7}, {%8,%9}, {%0,%1,%2,%3};"
                 : "+f"(d[0]), "+f"(d[1]), "+f"(d[2]), "+f"(d[3])
                 : "r"(a[0]), "r"(a[1]), "r"(a[2]), "r"(a[3]), "r"(b[0]), "r"(b[1]));
}

// ---------------- split fp32 -> (hi, lo) bf16 ----------------
__global__ void k_split(const float* __restrict__ in, __nv_bfloat16* __restrict__ hi,
                        __nv_bfloat16* __restrict__ lo, int n4) {
    int i = blockIdx.x * blockDim.x + threadIdx.x;
    if (i >= n4) return;
    float4 v = ((const float4*)in)[i];
    __nv_bfloat16 h0 = __float2bfloat16(v.x);
    __nv_bfloat16 h1 = __float2bfloat16(v.y);
    __nv_bfloat16 h2 = __float2bfloat16(v.z);
    __nv_bfloat16 h3 = __float2bfloat16(v.w);
    __nv_bfloat16 l0 = __float2bfloat16(v.x - __bfloat162float(h0));
    __nv_bfloat16 l1 = __float2bfloat16(v.y - __bfloat162float(h1));
    __nv_bfloat16 l2 = __float2bfloat16(v.z - __bfloat162float(h2));
    __nv_bfloat16 l3 = __float2bfloat16(v.w - __bfloat162float(h3));
    __nv_bfloat162* hp = (__nv_bfloat162*)hi;
    __nv_bfloat162* lp = (__nv_bfloat162*)lo;
    hp[i * 2]     = __nv_bfloat162(h0, h1);
    hp[i * 2 + 1] = __nv_bfloat162(h2, h3);
    lp[i * 2]     = __nv_bfloat162(l0, l1);
    lp[i * 2 + 1] = __nv_bfloat162(l2, l3);
}

// ---------------- HMMA split-bf16 GEMM ----------------
// C[M][N] = A[M][K] * B[N][K]^T + bias, via D += Ah*Bh + Ah*Bl + Al*Bh.
// 128x128 CTA tile, K-chunk 32, 8 warps (2Mx4N, warp tile 64x32), cp.async
// double-buffered smem. Tiles stored [128 rows][64B] with XOR swizzle:
// 16B-chunk' = chunk ^ ((row>>1)&3)  -> conflict-free stores and ldmatrix.
#define GT_TILE  8192                         // one 128x32 bf16 tile
#define GT_BUF   (4 * GT_TILE)                // Ah, Al, Bh, Bl = 32 KB
#define GT_TOTAL (2 * GT_BUF)                 // 64 KB double-buffered

__global__ __launch_bounds__(256, 1) void k_gemm_hmma(
    const __nv_bfloat16* __restrict__ Ahi, const __nv_bfloat16* __restrict__ Alo,
    const __nv_bfloat16* __restrict__ Bhi, const __nv_bfloat16* __restrict__ Blo,
    const float* __restrict__ bias, float* __restrict__ C,
    int M, int N, int K) {
    extern __shared__ char smem[];
    const uint32_t sb = smem_u32(smem);
    const int tid = threadIdx.x;
    const int wid = tid >> 5, l = tid & 31;
    const int bm = blockIdx.y * 128;
    const int bn = blockIdx.x * 128;
    const int wm = (wid >> 2) * 64;            // warp M offset in tile
    const int wn = (wid & 3) * 32;             // warp N offset in tile

    float acc[4][4][4];
    #pragma unroll
    for (int a = 0; a < 4; a++)
        #pragma unroll
        for (int b = 0; b < 4; b++)
            #pragma unroll
            for (int c = 0; c < 4; c++) acc[a][b][c] = 0.f;

    const int NCH = K >> 5;                    // chunks of 32

    auto load_chunk = [&](int c, int buf) {
        const int k0 = c * 32;
        const uint32_t sbase = sb + buf * GT_BUF;
        #pragma unroll
        for (int i = 0; i < 2; i++) {
            int e = tid + i * 256;             // 0..511
            int row = e >> 2;
            int ch = e & 3;
            uint32_t soff = row * 64 + ((ch ^ ((row >> 1) & 3)) << 4);
            size_t ga = (size_t)(bm + row) * K + k0 + ch * 8;
            size_t gb = (size_t)(bn + row) * K + k0 + ch * 8;
            CP_ASYNC16(sbase + 0 * GT_TILE + soff, (const char*)(Ahi + ga));
            CP_ASYNC16(sbase + 1 * GT_TILE + soff, (const char*)(Alo + ga));
            CP_ASYNC16(sbase + 2 * GT_TILE + soff, (const char*)(Bhi + gb));
            CP_ASYNC16(sbase + 3 * GT_TILE + soff, (const char*)(Blo + gb));
        }
    };

    auto compute = [&](int buf) {
        const uint32_t sbase = sb + buf * GT_BUF;
        #pragma unroll
        for (int ks = 0; ks < 2; ks++) {
            uint32_t ah[4][4], al[4][4], bh[4][2], bl[4][2];
            // A fragments: lane l -> group g=l>>3; row += (g&1)*8; chunk += (l>=16)
            const int ar_l = wm + ((l >> 3) & 1) * 8 + (l & 7);
            const int ach = ks * 2 + (l >> 4);
            #pragma unroll
            for (int mf = 0; mf < 4; mf++) {
                int r = ar_l + mf * 16;
                uint32_t soff = r * 64 + ((ach ^ ((r >> 1) & 3)) << 4);
                ldm_x4(ah[mf], sbase + 0 * GT_TILE + soff);
                ldm_x4(al[mf], sbase + 1 * GT_TILE + soff);
            }
            // B fragments (.x2 uses lanes 0-15): row = n, chunk = k-halves
            const int l16 = l & 15;
            const int br_l = wn + (l16 & 7);
            const int bch = ks * 2 + (l16 >> 3);
            #pragma unroll
            for (int nf = 0; nf < 4; nf++) {
                int r = br_l + nf * 8;
                uint32_t soff = r * 64 + ((bch ^ ((r >> 1) & 3)) << 4);
                ldm_x2(bh[nf], sbase + 2 * GT_TILE + soff);
                ldm_x2(bl[nf], sbase + 3 * GT_TILE + soff);
            }
            #pragma unroll
            for (int mf = 0; mf < 4; mf++)
                #pragma unroll
                for (int nf = 0; nf < 4; nf++) {
                    mma_bf16(acc[mf][nf], ah[mf], bh[nf]);
                    mma_bf16(acc[mf][nf], ah[mf], bl[nf]);
                    mma_bf16(acc[mf][nf], al[mf], bh[nf]);
                }
        }
    };

    load_chunk(0, 0);
    CP_COMMIT();
    for (int c = 0; c < NCH; c++) {
        if (c + 1 < NCH) load_chunk(c + 1, (c + 1) & 1);
        CP_COMMIT();
        CP_WAIT1();
        __syncthreads();
        compute(c & 1);
        __syncthreads();
    }

    // epilogue: d0,d1 -> (row, col..col+1); d2,d3 -> (row+8, ...)
    const int rbase = bm + wm + (l >> 2);
    const int cbase = bn + wn + (l & 3) * 2;
    #pragma unroll
    for (int mf = 0; mf < 4; mf++) {
        int r0 = rbase + mf * 16;
        #pragma unroll
        for (int nf = 0; nf < 4; nf++) {
            int cc = cbase + nf * 8;
            float2 bv = *(const float2*)&bias[cc];
            float2 v0, v1;
            v0.x = acc[mf][nf][0] + bv.x;
            v0.y = acc[mf][nf][1] + bv.y;
            v1.x = acc[mf][nf][2] + bv.x;
            v1.y = acc[mf][nf][3] + bv.y;
            *(float2*)&C[(size_t)r0 * N + cc] = v0;
            *(float2*)&C[(size_t)(r0 + 8) * N + cc] = v1;
        }
    }
}

// ---------------- local attention (fp32, unchanged) ----------------
__global__ __launch_bounds__(256) void k_local_attn(const float* __restrict__ qkv,
                                                    float* __restrict__ attn) {
    __shared__ float Ks[64][64];
    __shared__ float Vs[64][64];
    const int g = blockIdx.x, h = blockIdx.y, b = blockIdx.z;
    const int tid = threadIdx.x;
    const int qn = g * WIN + tid;

    const float* qrow = qkv + ((size_t)b * SEQ + qn) * QKVDIM + h * HDIM;
    float q[HDIM];
    #pragma unroll
    for (int i = 0; i < 16; i++) *(float4*)&q[i * 4] = *(const float4*)&qrow[i * 4];

    float m = -1e30f, l = 0.f;
    float o[HDIM];
    #pragma unroll
    for (int d = 0; d < HDIM; d++) o[d] = 0.f;

    const int c0 = (g == 0) ? 2 : 0;
    const int c1 = (g == NGRP - 1) ? 6 : 8;

    for (int c = c0; c < c1; c++) {
        const int base = g * WIN - EXT + c * 64;
        __syncthreads();
        #pragma unroll
        for (int i = 0; i < 4; i++) {
            int idx = tid * 4 + i;
            int row = idx >> 4;
            int col = (idx & 15) * 4;
            const float* kp = qkv + ((size_t)b * SEQ + base + row) * QKVDIM + DIM + h * HDIM + col;
            *(float4*)&Ks[row][col] = *(const float4*)kp;
            *(float4*)&Vs[row][col] = *(const float4*)(kp + DIM);
        }
        __syncthreads();

        for (int kk = 0; kk < 64; kk++) {
            float s0 = 0.f, s1 = 0.f, s2 = 0.f, s3 = 0.f;
            #pragma unroll
            for (int d4 = 0; d4 < 16; d4++) {
                float4 kv = *(float4*)&Ks[kk][d4 * 4];
                s0 += q[d4 * 4 + 0] * kv.x;
                s1 += q[d4 * 4 + 1] * kv.y;
                s2 += q[d4 * 4 + 2] * kv.z;
                s3 += q[d4 * 4 + 3] * kv.w;
            }
            float s = ((s0 + s1) + (s2 + s3)) * ATT_SCALE;
            if (s > m) {
                float corr = __expf(m - s);
                l *= corr;
                #pragma unroll
                for (int d = 0; d < HDIM; d++) o[d] *= corr;
                m = s;
            }
            float p = __expf(s - m);
            l += p;
            #pragma unroll
            for (int d4 = 0; d4 < 16; d4++) {
                float4 vv = *(float4*)&Vs[kk][d4 * 4];
                o[d4 * 4 + 0] += p * vv.x;
                o[d4 * 4 + 1] += p * vv.y;
                o[d4 * 4 + 2] += p * vv.z;
                o[d4 * 4 + 3] += p * vv.w;
            }
        }
    }

    const float inv = 1.f / l;
    float* op = attn + ((size_t)b * SEQ + qn) * DIM + h * HDIM;
    #pragma unroll
    for (int i = 0; i < 16; i++) {
        float4 v;
        v.x = o[i * 4 + 0] * inv;
        v.y = o[i * 4 + 1] * inv;
        v.z = o[i * 4 + 2] * inv;
        v.w = o[i * 4 + 3] * inv;
        *(float4*)&op[i * 4] = v;
    }
}

// ---------------- launch ----------------
extern "C" void kernel_launch(void* const* d_in, const int* in_sizes, int n_in,
                              void* d_out, int out_size) {
    const float* x      = (const float*)d_in[0];
    const float* w_qkv  = (const float*)d_in[1];
    const float* b_qkv  = (const float*)d_in[2];
    const float* w_proj = (const float*)d_in[3];
    const float* b_proj = (const float*)d_in[4];
    float* out = (float*)d_out;

    float *qkv, *attn;
    __nv_bfloat16 *xh, *xl, *wqh, *wql, *ah, *al, *wph, *wpl;
    cudaGetSymbolAddress((void**)&qkv,  g_qkv);
    cudaGetSymbolAddress((void**)&attn, g_attn);
    cudaGetSymbolAddress((void**)&xh,   g_x_hi);
    cudaGetSymbolAddress((void**)&xl,   g_x_lo);
    cudaGetSymbolAddress((void**)&wqh,  g_wqkv_hi);
    cudaGetSymbolAddress((void**)&wql,  g_wqkv_lo);
    cudaGetSymbolAddress((void**)&ah,   g_attn_hi);
    cudaGetSymbolAddress((void**)&al,   g_attn_lo);
    cudaGetSymbolAddress((void**)&wph,  g_wproj_hi);
    cudaGetSymbolAddress((void**)&wpl,  g_wproj_lo);

    cudaFuncSetAttribute(k_gemm_hmma, cudaFuncAttributeMaxDynamicSharedMemorySize, GT_TOTAL);

    // 1. precision splits
    k_split<<<(MROWS * DIM / 4 + 255) / 256, 256>>>(x, xh, xl, MROWS * DIM / 4);
    k_split<<<(QKVDIM * DIM / 4 + 255) / 256, 256>>>(w_qkv, wqh, wql, QKVDIM * DIM / 4);
    k_split<<<(DIM * DIM / 4 + 255) / 256, 256>>>(w_proj, wph, wpl, DIM * DIM / 4);

    // 2. QKV projection (HMMA tensor cores)
    k_gemm_hmma<<<dim3(QKVDIM / 128, MROWS / 128), 256, GT_TOTAL>>>(
        xh, xl, wqh, wql, b_qkv, qkv, MROWS, QKVDIM, DIM);

    // 3. local windowed attention
    k_local_attn<<<dim3(NGRP, NHEAD, BATCH), 256>>>(qkv, attn);

    // 4. split attention output, then output projection (HMMA tensor cores)
    k_split<<<(MROWS * DIM / 4 + 255) / 256, 256>>>(attn, ah, al, MROWS * DIM / 4);
    k_gemm_hmma<<<dim3(DIM / 128, MROWS / 128), 256, GT_TOTAL>>>(
        ah, al, wph, wpl, b_proj, out, MROWS, DIM, DIM);
}

// round 6
// speedup vs baseline: 2.6962x; 1.6099x over previous
#include <cuda_runtime.h>
#include <cuda_bf16.h>
#include <cstdint>

// Problem constants
#define BATCH 4
#define SEQ   4096
#define DIM   1024
#define NHEAD 16
#define HDIM  64
#define WIN   256
#define EXT   128
#define NGRP  (SEQ / WIN)          // 16
#define QKVDIM (3 * DIM)           // 3072
#define MROWS (BATCH * SEQ)        // 16384
#define ATT_SCALE 0.125f           // 64^-0.5

// ---------------- scratch (allocation-free: __device__ globals) ----------------
__device__ __nv_bfloat16 g_qkvh[(size_t)MROWS * QKVDIM];   // 96 MB
__device__ __nv_bfloat16 g_qkvl[(size_t)MROWS * QKVDIM];   // 96 MB
__device__ __nv_bfloat16 g_x_hi[(size_t)MROWS * DIM];      // 32 MB
__device__ __nv_bfloat16 g_x_lo[(size_t)MROWS * DIM];
__device__ __nv_bfloat16 g_wqkv_hi[(size_t)QKVDIM * DIM];  // 6 MB
__device__ __nv_bfloat16 g_wqkv_lo[(size_t)QKVDIM * DIM];
__device__ __nv_bfloat16 g_attn_hi[(size_t)MROWS * DIM];   // 32 MB
__device__ __nv_bfloat16 g_attn_lo[(size_t)MROWS * DIM];
__device__ __nv_bfloat16 g_wproj_hi[(size_t)DIM * DIM];    // 2 MB
__device__ __nv_bfloat16 g_wproj_lo[(size_t)DIM * DIM];

// ================= PTX helpers (base sm_103: NO 'a'-gated instructions) =================
__device__ __forceinline__ uint32_t smem_u32(const void* p) {
    uint32_t a;
    asm("{ .reg .u64 t; cvta.to.shared.u64 t, %1; cvt.u32.u64 %0, t; }" : "=r"(a) : "l"(p));
    return a;
}
#define CP_ASYNC16(s, g) \
    asm volatile("cp.async.cg.shared.global [%0], [%1], 16;" :: "r"(s), "l"(g))
#define CP_COMMIT() asm volatile("cp.async.commit_group;" ::: "memory")
#define CP_WAIT1()  asm volatile("cp.async.wait_group 1;" ::: "memory")

__device__ __forceinline__ void ldm_x4(uint32_t* r, uint32_t a) {
    asm volatile("ldmatrix.sync.aligned.m8n8.x4.shared.b16 {%0,%1,%2,%3}, [%4];"
                 : "=r"(r[0]), "=r"(r[1]), "=r"(r[2]), "=r"(r[3]) : "r"(a));
}
__device__ __forceinline__ void ldm_x4_t(uint32_t* r, uint32_t a) {
    asm volatile("ldmatrix.sync.aligned.m8n8.x4.trans.shared.b16 {%0,%1,%2,%3}, [%4];"
                 : "=r"(r[0]), "=r"(r[1]), "=r"(r[2]), "=r"(r[3]) : "r"(a));
}
__device__ __forceinline__ void ldm_x2(uint32_t* r, uint32_t a) {
    asm volatile("ldmatrix.sync.aligned.m8n8.x2.shared.b16 {%0,%1}, [%2];"
                 : "=r"(r[0]), "=r"(r[1]) : "r"(a));
}
__device__ __forceinline__ void mma_bf16(float* d, const uint32_t* a, const uint32_t* b) {
    asm volatile("mma.sync.aligned.m16n8k16.row.col.f32.bf16.bf16.f32 "
                 "{%0,%1,%2,%3}, {%4,%5,%6,%7}, {%8,%9}, {%0,%1,%2,%3};"
                 : "+f"(d[0]), "+f"(d[1]), "+f"(d[2]), "+f"(d[3])
                 : "r"(a[0]), "r"(a[1]), "r"(a[2]), "r"(a[3]), "r"(b[0]), "r"(b[1]));
}
// split two floats into packed bf16 hi and lo pairs (x = first arg = low half)
__device__ __forceinline__ void split2(uint32_t& hi, uint32_t& lo, float a, float b) {
    __nv_bfloat16 ha = __float2bfloat16(a), hb = __float2bfloat16(b);
    __nv_bfloat16 la = __float2bfloat16(a - __bfloat162float(ha));
    __nv_bfloat16 lb = __float2bfloat16(b - __bfloat162float(hb));
    __nv_bfloat162 hh(ha, hb), ll(la, lb);
    hi = *(uint32_t*)&hh;
    lo = *(uint32_t*)&ll;
}

// ---------------- split fp32 -> (hi, lo) bf16 ----------------
__global__ void k_split(const float* __restrict__ in, __nv_bfloat16* __restrict__ hi,
                        __nv_bfloat16* __restrict__ lo, int n4) {
    int i = blockIdx.x * blockDim.x + threadIdx.x;
    if (i >= n4) return;
    float4 v = ((const float4*)in)[i];
    uint32_t h0, l0, h1, l1;
    split2(h0, l0, v.x, v.y);
    split2(h1, l1, v.z, v.w);
    uint2* hp = (uint2*)hi;
    uint2* lp = (uint2*)lo;
    hp[i] = make_uint2(h0, h1);
    lp[i] = make_uint2(l0, l1);
}

// ---------------- HMMA split-bf16 GEMM ----------------
// C = A[M][K] * B[N][K]^T + bias, via D += Ah*Bh + Ah*Bl + Al*Bh.
// SPLIT_OUT: write bf16 hi/lo pair instead of fp32.
#define GT_TILE  8192
#define GT_BUF   (4 * GT_TILE)                // 32 KB
#define GT_TOTAL (2 * GT_BUF)                 // 64 KB

template <bool SPLIT_OUT>
__global__ __launch_bounds__(256, 1) void k_gemm_hmma(
    const __nv_bfloat16* __restrict__ Ahi, const __nv_bfloat16* __restrict__ Alo,
    const __nv_bfloat16* __restrict__ Bhi, const __nv_bfloat16* __restrict__ Blo,
    const float* __restrict__ bias, float* __restrict__ C,
    __nv_bfloat16* __restrict__ Chi, __nv_bfloat16* __restrict__ Clo,
    int M, int N, int K) {
    extern __shared__ char smem[];
    const uint32_t sb = smem_u32(smem);
    const int tid = threadIdx.x;
    const int wid = tid >> 5, l = tid & 31;
    const int bm = blockIdx.y * 128;
    const int bn = blockIdx.x * 128;
    const int wm = (wid >> 2) * 64;
    const int wn = (wid & 3) * 32;

    float acc[4][4][4];
    #pragma unroll
    for (int a = 0; a < 4; a++)
        #pragma unroll
        for (int b = 0; b < 4; b++)
            #pragma unroll
            for (int c = 0; c < 4; c++) acc[a][b][c] = 0.f;

    const int NCH = K >> 5;

    auto load_chunk = [&](int c, int buf) {
        const int k0 = c * 32;
        const uint32_t sbase = sb + buf * GT_BUF;
        #pragma unroll
        for (int i = 0; i < 2; i++) {
            int e = tid + i * 256;
            int row = e >> 2;
            int ch = e & 3;
            uint32_t soff = row * 64 + ((ch ^ ((row >> 1) & 3)) << 4);
            size_t ga = (size_t)(bm + row) * K + k0 + ch * 8;
            size_t gb = (size_t)(bn + row) * K + k0 + ch * 8;
            CP_ASYNC16(sbase + 0 * GT_TILE + soff, (const char*)(Ahi + ga));
            CP_ASYNC16(sbase + 1 * GT_TILE + soff, (const char*)(Alo + ga));
            CP_ASYNC16(sbase + 2 * GT_TILE + soff, (const char*)(Bhi + gb));
            CP_ASYNC16(sbase + 3 * GT_TILE + soff, (const char*)(Blo + gb));
        }
    };

    auto compute = [&](int buf) {
        const uint32_t sbase = sb + buf * GT_BUF;
        #pragma unroll
        for (int ks = 0; ks < 2; ks++) {
            uint32_t ah[4][4], al[4][4], bh[4][2], bl[4][2];
            const int ar_l = wm + ((l >> 3) & 1) * 8 + (l & 7);
            const int ach = ks * 2 + (l >> 4);
            #pragma unroll
            for (int mf = 0; mf < 4; mf++) {
                int r = ar_l + mf * 16;
                uint32_t soff = r * 64 + ((ach ^ ((r >> 1) & 3)) << 4);
                ldm_x4(ah[mf], sbase + 0 * GT_TILE + soff);
                ldm_x4(al[mf], sbase + 1 * GT_TILE + soff);
            }
            const int l16 = l & 15;
            const int br_l = wn + (l16 & 7);
            const int bch = ks * 2 + (l16 >> 3);
            #pragma unroll
            for (int nf = 0; nf < 4; nf++) {
                int r = br_l + nf * 8;
                uint32_t soff = r * 64 + ((bch ^ ((r >> 1) & 3)) << 4);
                ldm_x2(bh[nf], sbase + 2 * GT_TILE + soff);
                ldm_x2(bl[nf], sbase + 3 * GT_TILE + soff);
            }
            #pragma unroll
            for (int mf = 0; mf < 4; mf++)
                #pragma unroll
                for (int nf = 0; nf < 4; nf++) {
                    mma_bf16(acc[mf][nf], ah[mf], bh[nf]);
                    mma_bf16(acc[mf][nf], ah[mf], bl[nf]);
                    mma_bf16(acc[mf][nf], al[mf], bh[nf]);
                }
        }
    };

    load_chunk(0, 0);
    CP_COMMIT();
    for (int c = 0; c < NCH; c++) {
        if (c + 1 < NCH) load_chunk(c + 1, (c + 1) & 1);
        CP_COMMIT();
        CP_WAIT1();
        __syncthreads();
        compute(c & 1);
        __syncthreads();
    }

    const int rbase = bm + wm + (l >> 2);
    const int cbase = bn + wn + (l & 3) * 2;
    #pragma unroll
    for (int mf = 0; mf < 4; mf++) {
        int r0 = rbase + mf * 16;
        #pragma unroll
        for (int nf = 0; nf < 4; nf++) {
            int cc = cbase + nf * 8;
            float2 bv = *(const float2*)&bias[cc];
            float v00 = acc[mf][nf][0] + bv.x, v01 = acc[mf][nf][1] + bv.y;
            float v10 = acc[mf][nf][2] + bv.x, v11 = acc[mf][nf][3] + bv.y;
            if (SPLIT_OUT) {
                uint32_t h, lo;
                split2(h, lo, v00, v01);
                *(uint32_t*)(Chi + (size_t)r0 * N + cc) = h;
                *(uint32_t*)(Clo + (size_t)r0 * N + cc) = lo;
                split2(h, lo, v10, v11);
                *(uint32_t*)(Chi + (size_t)(r0 + 8) * N + cc) = h;
                *(uint32_t*)(Clo + (size_t)(r0 + 8) * N + cc) = lo;
            } else {
                *(float2*)&C[(size_t)r0 * N + cc] = make_float2(v00, v01);
                *(float2*)&C[(size_t)(r0 + 8) * N + cc] = make_float2(v10, v11);
            }
        }
    }
}

// ---------------- HMMA local attention ----------------
// CTA = 128 q rows of one (b,h,group-half). 8 warps x 16 q rows.
// K window processed in 64-key chunks (all-valid or all-invalid).
// QK: S = Qh*Kh + Qh*Kl + Ql*Kh  (B-frags = non-trans ldmatrix on K rows)
// PV: O += Ph*Vh + Ph*Vl + Pl*Vh (B-frags = trans ldmatrix on V rows)
// smem: Qh@0 Ql@16K | buf0@32K: Kh,Kl,Vh,Vl (8K each) | buf1@64K. total 96K.
#define AT_SMEM 98304

__global__ __launch_bounds__(256, 1) void k_attn_hmma(
    const __nv_bfloat16* __restrict__ qg_h, const __nv_bfloat16* __restrict__ qg_l,
    __nv_bfloat16* __restrict__ og_h, __nv_bfloat16* __restrict__ og_l) {
    extern __shared__ char smem[];
    const uint32_t sb = smem_u32(smem);
    const int half = blockIdx.x & 1, g = blockIdx.x >> 1;
    const int h = blockIdx.y, b = blockIdx.z;
    const int tid = threadIdx.x, wid = tid >> 5, l = tid & 31;
    const int qrow0 = b * SEQ + g * WIN + half * 128;   // CTA's first global q row
    const int wq = wid * 16;

    // ---- stage Q tiles (hi @ 0, lo @ 16K): 128 rows x 128B, swizzled ----
    #pragma unroll
    for (int j = 0; j < 8; j++) {
        int i = tid + j * 256;
        int t = i >> 10;                 // 0 = hi, 1 = lo
        int idx = i & 1023;
        int row = idx >> 3, ch = idx & 7;
        const __nv_bfloat16* src = (t ? qg_l : qg_h)
            + (size_t)(qrow0 + row) * QKVDIM + h * HDIM + ch * 8;
        CP_ASYNC16(sb + t * 16384 + row * 128 + ((ch ^ (row & 7)) << 4), src);
    }

    auto stage_kv = [&](int c, int buf) {
        const int kr0 = b * SEQ + g * WIN - EXT + c * 64;
        const uint32_t base = sb + 32768 + buf * 32768;
        #pragma unroll
        for (int j = 0; j < 8; j++) {
            int i = tid + j * 256;
            int t = i >> 9;             // 0 Kh 1 Kl 2 Vh 3 Vl
            int idx = i & 511;
            int row = idx >> 3, ch = idx & 7;
            const __nv_bfloat16* src = ((t & 1) ? qg_l : qg_h)
                + (size_t)(kr0 + row) * QKVDIM + ((t >> 1) ? 2 * DIM : DIM) + h * HDIM + ch * 8;
            CP_ASYNC16(base + t * 8192 + row * 128 + ((ch ^ (row & 7)) << 4), src);
        }
    };

    uint32_t qhf[4][4], qlf[4][4];      // A-frags per k-step (d dims)
    float o[8][4];
    #pragma unroll
    for (int nf = 0; nf < 8; nf++)
        #pragma unroll
        for (int j = 0; j < 4; j++) o[nf][j] = 0.f;
    float ma = -1e30f, mb = -1e30f, la = 0.f, lb = 0.f;

    const int c0 = (g == 0) ? 2 : 0;
    const int c1 = (g == NGRP - 1) ? 6 : 8;
    const int nch = c1 - c0;

    stage_kv(c0, 0);
    CP_COMMIT();
    for (int it = 0; it < nch; it++) {
        if (it + 1 < nch) stage_kv(c0 + it + 1, (it + 1) & 1);
        CP_COMMIT();
        CP_WAIT1();
        __syncthreads();
        if (it == 0) {
            // load Q A-frags once
            #pragma unroll
            for (int ks = 0; ks < 4; ks++) {
                int r = wq + (l & 7) + ((l >> 3) & 1) * 8;
                int c = 2 * ks + ((l >> 4) & 1);
                uint32_t off = r * 128 + ((c ^ (r & 7)) << 4);
                ldm_x4(qhf[ks], sb + off);
                ldm_x4(qlf[ks], sb + 16384 + off);
            }
        }
        const uint32_t kb = sb + 32768 + (it & 1) * 32768;

        // ---- QK: S[16q x 64k] per warp ----
        float s[8][4];
        #pragma unroll
        for (int nf = 0; nf < 8; nf++)
            #pragma unroll
            for (int j = 0; j < 4; j++) s[nf][j] = 0.f;
        #pragma unroll
        for (int ks = 0; ks < 4; ks++) {
            const int r = (l & 7) + ((l >> 4) & 1) * 8;
            const int c = 2 * ks + ((l >> 3) & 1);
            #pragma unroll
            for (int np = 0; np < 4; np++) {
                int rr = np * 16 + r;
                uint32_t off = rr * 128 + ((c ^ (rr & 7)) << 4);
                uint32_t bh[4], bl[4];
                ldm_x4(bh, kb + off);          // Kh
                ldm_x4(bl, kb + 8192 + off);   // Kl
                mma_bf16(s[2 * np],     qhf[ks], bh);
                mma_bf16(s[2 * np],     qhf[ks], bl);
                mma_bf16(s[2 * np],     qlf[ks], bh);
                mma_bf16(s[2 * np + 1], qhf[ks], bh + 2);
                mma_bf16(s[2 * np + 1], qhf[ks], bl + 2);
                mma_bf16(s[2 * np + 1], qlf[ks], bh + 2);
            }
        }

        // ---- online softmax (rows ra = wq + l>>2, rb = ra+8) ----
        float mxa = -1e30f, mxb = -1e30f;
        #pragma unroll
        for (int nf = 0; nf < 8; nf++) {
            mxa = fmaxf(mxa, fmaxf(s[nf][0], s[nf][1]));
            mxb = fmaxf(mxb, fmaxf(s[nf][2], s[nf][3]));
        }
        mxa = fmaxf(mxa, __shfl_xor_sync(0xffffffffu, mxa, 1));
        mxa = fmaxf(mxa, __shfl_xor_sync(0xffffffffu, mxa, 2));
        mxb = fmaxf(mxb, __shfl_xor_sync(0xffffffffu, mxb, 1));
        mxb = fmaxf(mxb, __shfl_xor_sync(0xffffffffu, mxb, 2));
        float nma = fmaxf(ma, mxa), nmb = fmaxf(mb, mxb);
        float ca = __expf((ma - nma) * ATT_SCALE);
        float cb = __expf((mb - nmb) * ATT_SCALE);
        ma = nma; mb = nmb;
        la *= ca; lb *= cb;
        #pragma unroll
        for (int nf = 0; nf < 8; nf++) {
            s[nf][0] = __expf((s[nf][0] - ma) * ATT_SCALE);
            s[nf][1] = __expf((s[nf][1] - ma) * ATT_SCALE);
            s[nf][2] = __expf((s[nf][2] - mb) * ATT_SCALE);
            s[nf][3] = __expf((s[nf][3] - mb) * ATT_SCALE);
            la += s[nf][0] + s[nf][1];
            lb += s[nf][2] + s[nf][3];
            o[nf][0] *= ca; o[nf][1] *= ca;
            o[nf][2] *= cb; o[nf][3] *= cb;
        }

        // ---- pack P into A-frags (hi/lo) ----
        uint32_t ph[4][4], pl[4][4];
        #pragma unroll
        for (int j = 0; j < 4; j++) {
            split2(ph[j][0], pl[j][0], s[2 * j][0],     s[2 * j][1]);
            split2(ph[j][1], pl[j][1], s[2 * j][2],     s[2 * j][3]);
            split2(ph[j][2], pl[j][2], s[2 * j + 1][0], s[2 * j + 1][1]);
            split2(ph[j][3], pl[j][3], s[2 * j + 1][2], s[2 * j + 1][3]);
        }

        // ---- PV: O += P * V ----
        #pragma unroll
        for (int ks = 0; ks < 4; ks++) {
            const int r = ks * 16 + (l & 7) + ((l >> 3) & 1) * 8;
            const int c = (l >> 4) & 1;
            #pragma unroll
            for (int dp = 0; dp < 4; dp++) {
                int cc = 2 * dp + c;
                uint32_t off = r * 128 + ((cc ^ (r & 7)) << 4);
                uint32_t vh[4], vl[4];
                ldm_x4_t(vh, kb + 16384 + off);   // Vh
                ldm_x4_t(vl, kb + 24576 + off);   // Vl
                mma_bf16(o[2 * dp],     ph[ks], vh);
                mma_bf16(o[2 * dp],     ph[ks], vl);
                mma_bf16(o[2 * dp],     pl[ks], vh);
                mma_bf16(o[2 * dp + 1], ph[ks], vh + 2);
                mma_bf16(o[2 * dp + 1], ph[ks], vl + 2);
                mma_bf16(o[2 * dp + 1], pl[ks], vh + 2);
            }
        }
        __syncthreads();
    }

    // ---- epilogue: normalize, split to bf16 hi/lo, store ----
    la += __shfl_xor_sync(0xffffffffu, la, 1);
    la += __shfl_xor_sync(0xffffffffu, la, 2);
    lb += __shfl_xor_sync(0xffffffffu, lb, 1);
    lb += __shfl_xor_sync(0xffffffffu, lb, 2);
    const float ia = 1.f / la, ib = 1.f / lb;
    const int ra = qrow0 + wq + (l >> 2);
    const int rb = ra + 8;
    const int colb = h * HDIM + 2 * (l & 3);
    #pragma unroll
    for (int nf = 0; nf < 8; nf++) {
        int cc = colb + nf * 8;
        uint32_t hi, lo;
        split2(hi, lo, o[nf][0] * ia, o[nf][1] * ia);
        *(uint32_t*)(og_h + (size_t)ra * DIM + cc) = hi;
        *(uint32_t*)(og_l + (size_t)ra * DIM + cc) = lo;
        split2(hi, lo, o[nf][2] * ib, o[nf][3] * ib);
        *(uint32_t*)(og_h + (size_t)rb * DIM + cc) = hi;
        *(uint32_t*)(og_l + (size_t)rb * DIM + cc) = lo;
    }
}

// ---------------- launch ----------------
extern "C" void kernel_launch(void* const* d_in, const int* in_sizes, int n_in,
                              void* d_out, int out_size) {
    const float* x      = (const float*)d_in[0];
    const float* w_qkv  = (const float*)d_in[1];
    const float* b_qkv  = (const float*)d_in[2];
    const float* w_proj = (const float*)d_in[3];
    const float* b_proj = (const float*)d_in[4];
    float* out = (float*)d_out;

    __nv_bfloat16 *qh, *ql, *xh, *xl, *wqh, *wql, *ah, *al, *wph, *wpl;
    cudaGetSymbolAddress((void**)&qh,  g_qkvh);
    cudaGetSymbolAddress((void**)&ql,  g_qkvl);
    cudaGetSymbolAddress((void**)&xh,  g_x_hi);
    cudaGetSymbolAddress((void**)&xl,  g_x_lo);
    cudaGetSymbolAddress((void**)&wqh, g_wqkv_hi);
    cudaGetSymbolAddress((void**)&wql, g_wqkv_lo);
    cudaGetSymbolAddress((void**)&ah,  g_attn_hi);
    cudaGetSymbolAddress((void**)&al,  g_attn_lo);
    cudaGetSymbolAddress((void**)&wph, g_wproj_hi);
    cudaGetSymbolAddress((void**)&wpl, g_wproj_lo);

    cudaFuncSetAttribute(k_gemm_hmma<true>,  cudaFuncAttributeMaxDynamicSharedMemorySize, GT_TOTAL);
    cudaFuncSetAttribute(k_gemm_hmma<false>, cudaFuncAttributeMaxDynamicSharedMemorySize, GT_TOTAL);
    cudaFuncSetAttribute(k_attn_hmma, cudaFuncAttributeMaxDynamicSharedMemorySize, AT_SMEM);

    // 1. precision splits of inputs
    k_split<<<(MROWS * DIM / 4 + 255) / 256, 256>>>(x, xh, xl, MROWS * DIM / 4);
    k_split<<<(QKVDIM * DIM / 4 + 255) / 256, 256>>>(w_qkv, wqh, wql, QKVDIM * DIM / 4);
    k_split<<<(DIM * DIM / 4 + 255) / 256, 256>>>(w_proj, wph, wpl, DIM * DIM / 4);

    // 2. QKV projection -> bf16 hi/lo directly
    k_gemm_hmma<true><<<dim3(QKVDIM / 128, MROWS / 128), 256, GT_TOTAL>>>(
        xh, xl, wqh, wql, b_qkv, nullptr, qh, ql, MROWS, QKVDIM, DIM);

    // 3. local windowed attention (HMMA) -> bf16 hi/lo
    k_attn_hmma<<<dim3(NGRP * 2, NHEAD, BATCH), 256, AT_SMEM>>>(qh, ql, ah, al);

    // 4. output projection -> fp32 out
    k_gemm_hmma<false><<<dim3(DIM / 128, MROWS / 128), 256, GT_TOTAL>>>(
        ah, al, wph, wpl, b_proj, out, nullptr, nullptr, MROWS, DIM, DIM);
}

// round 7
// speedup vs baseline: 2.7800x; 1.0311x over previous
#include <cuda_runtime.h>
#include <cuda_bf16.h>
#include <cstdint>

// Problem constants
#define BATCH 4
#define SEQ   4096
#define DIM   1024
#define NHEAD 16
#define HDIM  64
#define WIN   256
#define EXT   128
#define NGRP  (SEQ / WIN)          // 16
#define QKVDIM (3 * DIM)           // 3072
#define MROWS (BATCH * SEQ)        // 16384
#define ATT_SCALE 0.125f           // 64^-0.5

// ---------------- scratch (allocation-free: __device__ globals) ----------------
__device__ __nv_bfloat16 g_qkvh[(size_t)MROWS * QKVDIM];   // 96 MB
__device__ __nv_bfloat16 g_qkvl[(size_t)MROWS * QKVDIM];   // 96 MB
__device__ __nv_bfloat16 g_x_hi[(size_t)MROWS * DIM];      // 32 MB
__device__ __nv_bfloat16 g_x_lo[(size_t)MROWS * DIM];
__device__ __nv_bfloat16 g_wqkv_hi[(size_t)QKVDIM * DIM];  // 6 MB
__device__ __nv_bfloat16 g_wqkv_lo[(size_t)QKVDIM * DIM];
__device__ __nv_bfloat16 g_attn_hi[(size_t)MROWS * DIM];   // 32 MB
__device__ __nv_bfloat16 g_attn_lo[(size_t)MROWS * DIM];
__device__ __nv_bfloat16 g_wproj_hi[(size_t)DIM * DIM];    // 2 MB
__device__ __nv_bfloat16 g_wproj_lo[(size_t)DIM * DIM];

// ================= PTX helpers (base sm_103: NO 'a'-gated instructions) =================
__device__ __forceinline__ uint32_t smem_u32(const void* p) {
    uint32_t a;
    asm("{ .reg .u64 t; cvta.to.shared.u64 t, %1; cvt.u32.u64 %0, t; }" : "=r"(a) : "l"(p));
    return a;
}
#define CP_ASYNC16(s, g) \
    asm volatile("cp.async.cg.shared.global [%0], [%1], 16;" :: "r"(s), "l"(g))
#define CP_COMMIT() asm volatile("cp.async.commit_group;" ::: "memory")
#define CP_WAIT_GROUP(n) asm volatile("cp.async.wait_group %0;" :: "n"(n) : "memory")

__device__ __forceinline__ void ldm_x4(uint32_t* r, uint32_t a) {
    asm volatile("ldmatrix.sync.aligned.m8n8.x4.shared.b16 {%0,%1,%2,%3}, [%4];"
                 : "=r"(r[0]), "=r"(r[1]), "=r"(r[2]), "=r"(r[3]) : "r"(a));
}
__device__ __forceinline__ void ldm_x4_t(uint32_t* r, uint32_t a) {
    asm volatile("ldmatrix.sync.aligned.m8n8.x4.trans.shared.b16 {%0,%1,%2,%3}, [%4];"
                 : "=r"(r[0]), "=r"(r[1]), "=r"(r[2]), "=r"(r[3]) : "r"(a));
}
__device__ __forceinline__ void ldm_x2(uint32_t* r, uint32_t a) {
    asm volatile("ldmatrix.sync.aligned.m8n8.x2.shared.b16 {%0,%1}, [%2];"
                 : "=r"(r[0]), "=r"(r[1]) : "r"(a));
}
__device__ __forceinline__ void mma_bf16(float* d, const uint32_t* a, const uint32_t* b) {
    asm volatile("mma.sync.aligned.m16n8k16.row.col.f32.bf16.bf16.f32 "
                 "{%0,%1,%2,%3}, {%4,%5,%6,%7}, {%8,%9}, {%0,%1,%2,%3};"
                 : "+f"(d[0]), "+f"(d[1]), "+f"(d[2]), "+f"(d[3])
                 : "r"(a[0]), "r"(a[1]), "r"(a[2]), "r"(a[3]), "r"(b[0]), "r"(b[1]));
}
// split two floats into packed bf16 hi and lo pairs
__device__ __forceinline__ void split2(uint32_t& hi, uint32_t& lo, float a, float b) {
    __nv_bfloat16 ha = __float2bfloat16(a), hb = __float2bfloat16(b);
    __nv_bfloat16 la = __float2bfloat16(a - __bfloat162float(ha));
    __nv_bfloat16 lb = __float2bfloat16(b - __bfloat162float(hb));
    __nv_bfloat162 hh(ha, hb), ll(la, lb);
    hi = *(uint32_t*)&hh;
    lo = *(uint32_t*)&ll;
}

// ---------------- split fp32 -> (hi, lo) bf16 ----------------
__global__ void k_split(const float* __restrict__ in, __nv_bfloat16* __restrict__ hi,
                        __nv_bfloat16* __restrict__ lo, int n4) {
    int i = blockIdx.x * blockDim.x + threadIdx.x;
    if (i >= n4) return;
    float4 v = ((const float4*)in)[i];
    uint32_t h0, l0, h1, l1;
    split2(h0, l0, v.x, v.y);
    split2(h1, l1, v.z, v.w);
    uint2* hp = (uint2*)hi;
    uint2* lp = (uint2*)lo;
    hp[i] = make_uint2(h0, h1);
    lp[i] = make_uint2(l0, l1);
}

// ---------------- HMMA split-bf16 GEMM ----------------
// C = A[M][K] * B[N][K]^T + bias, via D += Ah*Bh + Ah*Bl + Al*Bh.
// 128x128 CTA tile, K-chunk 32, 8 warps (2Mx4N, warp 64x32).
// 4-stage cp.async ring, ONE __syncthreads per chunk (top-of-loop, after wait).
#define GT_TILE   8192
#define GT_BUF    (4 * GT_TILE)               // 32 KB per stage
#define GT_STAGES 4
#define GT_TOTAL  (GT_STAGES * GT_BUF)        // 128 KB

template <bool SPLIT_OUT>
__global__ __launch_bounds__(256, 1) void k_gemm_hmma(
    const __nv_bfloat16* __restrict__ Ahi, const __nv_bfloat16* __restrict__ Alo,
    const __nv_bfloat16* __restrict__ Bhi, const __nv_bfloat16* __restrict__ Blo,
    const float* __restrict__ bias, float* __restrict__ C,
    __nv_bfloat16* __restrict__ Chi, __nv_bfloat16* __restrict__ Clo,
    int M, int N, int K) {
    extern __shared__ char smem[];
    const uint32_t sb = smem_u32(smem);
    const int tid = threadIdx.x;
    const int wid = tid >> 5, l = tid & 31;
    const int bm = blockIdx.y * 128;
    const int bn = blockIdx.x * 128;
    const int wm = (wid >> 2) * 64;
    const int wn = (wid & 3) * 32;

    float acc[4][4][4];
    #pragma unroll
    for (int a = 0; a < 4; a++)
        #pragma unroll
        for (int b = 0; b < 4; b++)
            #pragma unroll
            for (int c = 0; c < 4; c++) acc[a][b][c] = 0.f;

    const int NCH = K >> 5;

    auto load_chunk = [&](int c, int buf) {
        const int k0 = c * 32;
        const uint32_t sbase = sb + buf * GT_BUF;
        #pragma unroll
        for (int i = 0; i < 2; i++) {
            int e = tid + i * 256;
            int row = e >> 2;
            int ch = e & 3;
            uint32_t soff = row * 64 + ((ch ^ ((row >> 1) & 3)) << 4);
            size_t ga = (size_t)(bm + row) * K + k0 + ch * 8;
            size_t gb = (size_t)(bn + row) * K + k0 + ch * 8;
            CP_ASYNC16(sbase + 0 * GT_TILE + soff, (const char*)(Ahi + ga));
            CP_ASYNC16(sbase + 1 * GT_TILE + soff, (const char*)(Alo + ga));
            CP_ASYNC16(sbase + 2 * GT_TILE + soff, (const char*)(Bhi + gb));
            CP_ASYNC16(sbase + 3 * GT_TILE + soff, (const char*)(Blo + gb));
        }
    };

    auto compute = [&](int buf) {
        const uint32_t sbase = sb + buf * GT_BUF;
        #pragma unroll
        for (int ks = 0; ks < 2; ks++) {
            uint32_t ah[4][4], al[4][4], bh[4][2], bl[4][2];
            const int ar_l = wm + ((l >> 3) & 1) * 8 + (l & 7);
            const int ach = ks * 2 + (l >> 4);
            #pragma unroll
            for (int mf = 0; mf < 4; mf++) {
                int r = ar_l + mf * 16;
                uint32_t soff = r * 64 + ((ach ^ ((r >> 1) & 3)) << 4);
                ldm_x4(ah[mf], sbase + 0 * GT_TILE + soff);
                ldm_x4(al[mf], sbase + 1 * GT_TILE + soff);
            }
            const int l16 = l & 15;
            const int br_l = wn + (l16 & 7);
            const int bch = ks * 2 + (l16 >> 3);
            #pragma unroll
            for (int nf = 0; nf < 4; nf++) {
                int r = br_l + nf * 8;
                uint32_t soff = r * 64 + ((bch ^ ((r >> 1) & 3)) << 4);
                ldm_x2(bh[nf], sbase + 2 * GT_TILE + soff);
                ldm_x2(bl[nf], sbase + 3 * GT_TILE + soff);
            }
            #pragma unroll
            for (int mf = 0; mf < 4; mf++)
                #pragma unroll
                for (int nf = 0; nf < 4; nf++) {
                    mma_bf16(acc[mf][nf], ah[mf], bh[nf]);
                    mma_bf16(acc[mf][nf], ah[mf], bl[nf]);
                    mma_bf16(acc[mf][nf], al[mf], bh[nf]);
                }
        }
    };

    // preload stages 0..2 (one commit group per chunk, uniformly)
    #pragma unroll
    for (int c = 0; c < GT_STAGES - 1; c++) {
        if (c < NCH) load_chunk(c, c);
        CP_COMMIT();
    }
    for (int c = 0; c < NCH; c++) {
        CP_WAIT_GROUP(GT_STAGES - 2);   // chunk c's group complete
        __syncthreads();                // all warps see it; stage (c-1)%4 free
        if (c + GT_STAGES - 1 < NCH) load_chunk(c + GT_STAGES - 1, (c + GT_STAGES - 1) & 3);
        CP_COMMIT();
        compute(c & 3);
    }

    const int rbase = bm + wm + (l >> 2);
    const int cbase = bn + wn + (l & 3) * 2;
    #pragma unroll
    for (int mf = 0; mf < 4; mf++) {
        int r0 = rbase + mf * 16;
        #pragma unroll
        for (int nf = 0; nf < 4; nf++) {
            int cc = cbase + nf * 8;
            float2 bv = *(const float2*)&bias[cc];
            float v00 = acc[mf][nf][0] + bv.x, v01 = acc[mf][nf][1] + bv.y;
            float v10 = acc[mf][nf][2] + bv.x, v11 = acc[mf][nf][3] + bv.y;
            if (SPLIT_OUT) {
                uint32_t h, lo;
                split2(h, lo, v00, v01);
                *(uint32_t*)(Chi + (size_t)r0 * N + cc) = h;
                *(uint32_t*)(Clo + (size_t)r0 * N + cc) = lo;
                split2(h, lo, v10, v11);
                *(uint32_t*)(Chi + (size_t)(r0 + 8) * N + cc) = h;
                *(uint32_t*)(Clo + (size_t)(r0 + 8) * N + cc) = lo;
            } else {
                *(float2*)&C[(size_t)r0 * N + cc] = make_float2(v00, v01);
                *(float2*)&C[(size_t)(r0 + 8) * N + cc] = make_float2(v10, v11);
            }
        }
    }
}

// ---------------- HMMA local attention ----------------
// CTA = 128 q rows of one (b,h,group-half). 8 warps x 16 q rows.
// 3-stage KV ring (32 KB/stage), one __syncthreads per 64-key chunk.
// smem: Qh@0 Ql@16K | KV stages @32K+buf*32K (Kh,Kl,Vh,Vl 8K each).
#define AT_SMEM (32768 + 3 * 32768)   // 128 KB

__global__ __launch_bounds__(256, 1) void k_attn_hmma(
    const __nv_bfloat16* __restrict__ qg_h, const __nv_bfloat16* __restrict__ qg_l,
    __nv_bfloat16* __restrict__ og_h, __nv_bfloat16* __restrict__ og_l) {
    extern __shared__ char smem[];
    const uint32_t sb = smem_u32(smem);
    const int half = blockIdx.x & 1, g = blockIdx.x >> 1;
    const int h = blockIdx.y, b = blockIdx.z;
    const int tid = threadIdx.x, wid = tid >> 5, l = tid & 31;
    const int qrow0 = b * SEQ + g * WIN + half * 128;
    const int wq = wid * 16;

    // ---- stage Q tiles (hi @ 0, lo @ 16K): joins first commit group ----
    #pragma unroll
    for (int j = 0; j < 8; j++) {
        int i = tid + j * 256;
        int t = i >> 10;
        int idx = i & 1023;
        int row = idx >> 3, ch = idx & 7;
        const __nv_bfloat16* src = (t ? qg_l : qg_h)
            + (size_t)(qrow0 + row) * QKVDIM + h * HDIM + ch * 8;
        CP_ASYNC16(sb + t * 16384 + row * 128 + ((ch ^ (row & 7)) << 4), src);
    }

    auto stage_kv = [&](int c, int buf) {
        const int kr0 = b * SEQ + g * WIN - EXT + c * 64;
        const uint32_t base = sb + 32768 + buf * 32768;
        #pragma unroll
        for (int j = 0; j < 8; j++) {
            int i = tid + j * 256;
            int t = i >> 9;             // 0 Kh 1 Kl 2 Vh 3 Vl
            int idx = i & 511;
            int row = idx >> 3, ch = idx & 7;
            const __nv_bfloat16* src = ((t & 1) ? qg_l : qg_h)
                + (size_t)(kr0 + row) * QKVDIM + ((t >> 1) ? 2 * DIM : DIM) + h * HDIM + ch * 8;
            CP_ASYNC16(base + t * 8192 + row * 128 + ((ch ^ (row & 7)) << 4), src);
        }
    };

    uint32_t qhf[4][4], qlf[4][4];
    float o[8][4];
    #pragma unroll
    for (int nf = 0; nf < 8; nf++)
        #pragma unroll
        for (int j = 0; j < 4; j++) o[nf][j] = 0.f;
    float ma = -1e30f, mb = -1e30f, la = 0.f, lb = 0.f;

    const int c0 = (g == 0) ? 2 : 0;
    const int c1 = (g == NGRP - 1) ? 6 : 8;
    const int nch = c1 - c0;

    // preload 2 stages (Q rides group 0)
    stage_kv(c0, 0);
    CP_COMMIT();
    if (nch > 1) stage_kv(c0 + 1, 1);
    CP_COMMIT();

    for (int it = 0; it < nch; it++) {
        CP_WAIT_GROUP(1);
        __syncthreads();
        {
            int nxt = it + 2;
            if (nxt < nch) {
                int bufn = nxt % 3;
                stage_kv(c0 + nxt, bufn);
            }
            CP_COMMIT();
        }
        if (it == 0) {
            #pragma unroll
            for (int ks = 0; ks < 4; ks++) {
                int r = wq + (l & 7) + ((l >> 3) & 1) * 8;
                int c = 2 * ks + ((l >> 4) & 1);
                uint32_t off = r * 128 + ((c ^ (r & 7)) << 4);
                ldm_x4(qhf[ks], sb + off);
                ldm_x4(qlf[ks], sb + 16384 + off);
            }
        }
        const uint32_t kb = sb + 32768 + (it % 3) * 32768;

        // ---- QK: S[16q x 64k] per warp ----
        float s[8][4];
        #pragma unroll
        for (int nf = 0; nf < 8; nf++)
            #pragma unroll
            for (int j = 0; j < 4; j++) s[nf][j] = 0.f;
        #pragma unroll
        for (int ks = 0; ks < 4; ks++) {
            const int r = (l & 7) + ((l >> 4) & 1) * 8;
            const int c = 2 * ks + ((l >> 3) & 1);
            #pragma unroll
            for (int np = 0; np < 4; np++) {
                int rr = np * 16 + r;
                uint32_t off = rr * 128 + ((c ^ (rr & 7)) << 4);
                uint32_t bh[4], bl[4];
                ldm_x4(bh, kb + off);
                ldm_x4(bl, kb + 8192 + off);
                mma_bf16(s[2 * np],     qhf[ks], bh);
                mma_bf16(s[2 * np],     qhf[ks], bl);
                mma_bf16(s[2 * np],     qlf[ks], bh);
                mma_bf16(s[2 * np + 1], qhf[ks], bh + 2);
                mma_bf16(s[2 * np + 1], qhf[ks], bl + 2);
                mma_bf16(s[2 * np + 1], qlf[ks], bh + 2);
            }
        }

        // ---- online softmax ----
        float mxa = -1e30f, mxb = -1e30f;
        #pragma unroll
        for (int nf = 0; nf < 8; nf++) {
            mxa = fmaxf(mxa, fmaxf(s[nf][0], s[nf][1]));
            mxb = fmaxf(mxb, fmaxf(s[nf][2], s[nf][3]));
        }
        mxa = fmaxf(mxa, __shfl_xor_sync(0xffffffffu, mxa, 1));
        mxa = fmaxf(mxa, __shfl_xor_sync(0xffffffffu, mxa, 2));
        mxb = fmaxf(mxb, __shfl_xor_sync(0xffffffffu, mxb, 1));
        mxb = fmaxf(mxb, __shfl_xor_sync(0xffffffffu, mxb, 2));
        float nma = fmaxf(ma, mxa), nmb = fmaxf(mb, mxb);
        float ca = __expf((ma - nma) * ATT_SCALE);
        float cb = __expf((mb - nmb) * ATT_SCALE);
        ma = nma; mb = nmb;
        la *= ca; lb *= cb;
        #pragma unroll
        for (int nf = 0; nf < 8; nf++) {
            s[nf][0] = __expf((s[nf][0] - ma) * ATT_SCALE);
            s[nf][1] = __expf((s[nf][1] - ma) * ATT_SCALE);
            s[nf][2] = __expf((s[nf][2] - mb) * ATT_SCALE);
            s[nf][3] = __expf((s[nf][3] - mb) * ATT_SCALE);
            la += s[nf][0] + s[nf][1];
            lb += s[nf][2] + s[nf][3];
            o[nf][0] *= ca; o[nf][1] *= ca;
            o[nf][2] *= cb; o[nf][3] *= cb;
        }

        // ---- pack P into A-frags (hi/lo) ----
        uint32_t ph[4][4], pl[4][4];
        #pragma unroll
        for (int j = 0; j < 4; j++) {
            split2(ph[j][0], pl[j][0], s[2 * j][0],     s[2 * j][1]);
            split2(ph[j][1], pl[j][1], s[2 * j][2],     s[2 * j][3]);
            split2(ph[j][2], pl[j][2], s[2 * j + 1][0], s[2 * j + 1][1]);
            split2(ph[j][3], pl[j][3], s[2 * j + 1][2], s[2 * j + 1][3]);
        }

        // ---- PV: O += P * V ----
        #pragma unroll
        for (int ks = 0; ks < 4; ks++) {
            const int r = ks * 16 + (l & 7) + ((l >> 3) & 1) * 8;
            const int c = (l >> 4) & 1;
            #pragma unroll
            for (int dp = 0; dp < 4; dp++) {
                int cc = 2 * dp + c;
                uint32_t off = r * 128 + ((cc ^ (r & 7)) << 4);
                uint32_t vh[4], vl[4];
                ldm_x4_t(vh, kb + 16384 + off);
                ldm_x4_t(vl, kb + 24576 + off);
                mma_bf16(o[2 * dp],     ph[ks], vh);
                mma_bf16(o[2 * dp],     ph[ks], vl);
                mma_bf16(o[2 * dp],     pl[ks], vh);
                mma_bf16(o[2 * dp + 1], ph[ks], vh + 2);
                mma_bf16(o[2 * dp + 1], ph[ks], vl + 2);
                mma_bf16(o[2 * dp + 1], pl[ks], vh + 2);
            }
        }
    }

    // ---- epilogue ----
    la += __shfl_xor_sync(0xffffffffu, la, 1);
    la += __shfl_xor_sync(0xffffffffu, la, 2);
    lb += __shfl_xor_sync(0xffffffffu, lb, 1);
    lb += __shfl_xor_sync(0xffffffffu, lb, 2);
    const float ia = 1.f / la, ib = 1.f / lb;
    const int ra = qrow0 + wq + (l >> 2);
    const int rb = ra + 8;
    const int colb = h * HDIM + 2 * (l & 3);
    #pragma unroll
    for (int nf = 0; nf < 8; nf++) {
        int cc = colb + nf * 8;
        uint32_t hi, lo;
        split2(hi, lo, o[nf][0] * ia, o[nf][1] * ia);
        *(uint32_t*)(og_h + (size_t)ra * DIM + cc) = hi;
        *(uint32_t*)(og_l + (size_t)ra * DIM + cc) = lo;
        split2(hi, lo, o[nf][2] * ib, o[nf][3] * ib);
        *(uint32_t*)(og_h + (size_t)rb * DIM + cc) = hi;
        *(uint32_t*)(og_l + (size_t)rb * DIM + cc) = lo;
    }
}

// ---------------- launch ----------------
extern "C" void kernel_launch(void* const* d_in, const int* in_sizes, int n_in,
                              void* d_out, int out_size) {
    const float* x      = (const float*)d_in[0];
    const float* w_qkv  = (const float*)d_in[1];
    const float* b_qkv  = (const float*)d_in[2];
    const float* w_proj = (const float*)d_in[3];
    const float* b_proj = (const float*)d_in[4];
    float* out = (float*)d_out;

    __nv_bfloat16 *qh, *ql, *xh, *xl, *wqh, *wql, *ah, *al, *wph, *wpl;
    cudaGetSymbolAddress((void**)&qh,  g_qkvh);
    cudaGetSymbolAddress((void**)&ql,  g_qkvl);
    cudaGetSymbolAddress((void**)&xh,  g_x_hi);
    cudaGetSymbolAddress((void**)&xl,  g_x_lo);
    cudaGetSymbolAddress((void**)&wqh, g_wqkv_hi);
    cudaGetSymbolAddress((void**)&wql, g_wqkv_lo);
    cudaGetSymbolAddress((void**)&ah,  g_attn_hi);
    cudaGetSymbolAddress((void**)&al,  g_attn_lo);
    cudaGetSymbolAddress((void**)&wph, g_wproj_hi);
    cudaGetSymbolAddress((void**)&wpl, g_wproj_lo);

    cudaFuncSetAttribute(k_gemm_hmma<true>,  cudaFuncAttributeMaxDynamicSharedMemorySize, GT_TOTAL);
    cudaFuncSetAttribute(k_gemm_hmma<false>, cudaFuncAttributeMaxDynamicSharedMemorySize, GT_TOTAL);
    cudaFuncSetAttribute(k_attn_hmma, cudaFuncAttributeMaxDynamicSharedMemorySize, AT_SMEM);

    // 1. precision splits of inputs
    k_split<<<(MROWS * DIM / 4 + 255) / 256, 256>>>(x, xh, xl, MROWS * DIM / 4);
    k_split<<<(QKVDIM * DIM / 4 + 255) / 256, 256>>>(w_qkv, wqh, wql, QKVDIM * DIM / 4);
    k_split<<<(DIM * DIM / 4 + 255) / 256, 256>>>(w_proj, wph, wpl, DIM * DIM / 4);

    // 2. QKV projection -> bf16 hi/lo directly
    k_gemm_hmma<true><<<dim3(QKVDIM / 128, MROWS / 128), 256, GT_TOTAL>>>(
        xh, xl, wqh, wql, b_qkv, nullptr, qh, ql, MROWS, QKVDIM, DIM);

    // 3. local windowed attention (HMMA) -> bf16 hi/lo
    k_attn_hmma<<<dim3(NGRP * 2, NHEAD, BATCH), 256, AT_SMEM>>>(qh, ql, ah, al);

    // 4. output projection -> fp32 out
    k_gemm_hmma<false><<<dim3(DIM / 128, MROWS / 128), 256, GT_TOTAL>>>(
        ah, al, wph, wpl, b_proj, out, nullptr, nullptr, MROWS, DIM, DIM);
}

// round 9
// speedup vs baseline: 7.6259x; 2.7432x over previous
#include <cuda_runtime.h>
#include <cuda_fp16.h>
#include <cstdint>

// Problem constants
#define BATCH 4
#define SEQ   4096
#define DIM   1024
#define NHEAD 16
#define HDIM  64
#define WIN   256
#define EXT   128
#define NGRP  (SEQ / WIN)          // 16
#define QKVDIM (3 * DIM)           // 3072
#define MROWS (BATCH * SEQ)        // 16384
#define ATT_SCALE 0.125f           // 64^-0.5

// ---------------- scratch (allocation-free: __device__ globals) ----------------
__device__ __half g_qkvh[(size_t)MROWS * QKVDIM];   // 96 MB
__device__ __half g_xh[(size_t)MROWS * DIM];        // 32 MB
__device__ __half g_wqkvh[(size_t)QKVDIM * DIM];    // 6 MB
__device__ __half g_attnh[(size_t)MROWS * DIM];     // 32 MB
__device__ __half g_wprojh[(size_t)DIM * DIM];      // 2 MB

// ================= PTX helpers (base sm_103: NO 'a'-gated instructions) =================
__device__ __forceinline__ uint32_t smem_u32(const void* p) {
    uint32_t a;
    asm("{ .reg .u64 t; cvta.to.shared.u64 t, %1; cvt.u32.u64 %0, t; }" : "=r"(a) : "l"(p));
    return a;
}
#define CP_ASYNC16(s, g) \
    asm volatile("cp.async.cg.shared.global [%0], [%1], 16;" :: "r"(s), "l"(g))
#define CP_COMMIT() asm volatile("cp.async.commit_group;" ::: "memory")
#define CP_WAIT_GROUP(n) asm volatile("cp.async.wait_group %0;" :: "n"(n) : "memory")

__device__ __forceinline__ void ldm_x4(uint32_t* r, uint32_t a) {
    asm volatile("ldmatrix.sync.aligned.m8n8.x4.shared.b16 {%0,%1,%2,%3}, [%4];"
                 : "=r"(r[0]), "=r"(r[1]), "=r"(r[2]), "=r"(r[3]) : "r"(a));
}
__device__ __forceinline__ void ldm_x4_t(uint32_t* r, uint32_t a) {
    asm volatile("ldmatrix.sync.aligned.m8n8.x4.trans.shared.b16 {%0,%1,%2,%3}, [%4];"
                 : "=r"(r[0]), "=r"(r[1]), "=r"(r[2]), "=r"(r[3]) : "r"(a));
}
__device__ __forceinline__ void ldm_x2(uint32_t* r, uint32_t a) {
    asm volatile("ldmatrix.sync.aligned.m8n8.x2.shared.b16 {%0,%1}, [%2];"
                 : "=r"(r[0]), "=r"(r[1]) : "r"(a));
}
__device__ __forceinline__ void mma_f16(float* d, const uint32_t* a, const uint32_t* b) {
    asm volatile("mma.sync.aligned.m16n8k16.row.col.f32.f16.f16.f32 "
                 "{%0,%1,%2,%3}, {%4,%5,%6,%7}, {%8,%9}, {%0,%1,%2,%3};"
                 : "+f"(d[0]), "+f"(d[1]), "+f"(d[2]), "+f"(d[3])
                 : "r"(a[0]), "r"(a[1]), "r"(a[2]), "r"(a[3]), "r"(b[0]), "r"(b[1]));
}
__device__ __forceinline__ uint32_t pack2(float a, float b) {
    __half2 h = __floats2half2_rn(a, b);
    return *(uint32_t*)&h;
}

// ---------------- convert fp32 -> fp16 ----------------
__global__ void k_cvt(const float* __restrict__ in, __half* __restrict__ out, int n4) {
    int i = blockIdx.x * blockDim.x + threadIdx.x;
    if (i >= n4) return;
    float4 v = ((const float4*)in)[i];
    uint2* op = (uint2*)out;
    op[i] = make_uint2(pack2(v.x, v.y), pack2(v.z, v.w));
}

// ---------------- HMMA fp16 GEMM ----------------
// C = A[M][K] * B[N][K]^T + bias. 128x128 CTA tile, K-chunk 64,
// 8 warps (2Mx4N, warp 64x32), 3-stage cp.async ring, 2 CTAs/SM.
// Tile layout: 128 rows x 128B, swizzle: off = r*128 + ((c16 ^ (r&7))<<4).
#define GT_TILE   16384                       // one 128x64 fp16 tile
#define GT_BUF    (2 * GT_TILE)               // A + B = 32 KB per stage
#define GT_STAGES 3
#define GT_TOTAL  (GT_STAGES * GT_BUF)        // 96 KB

template <bool HALF_OUT>
__global__ __launch_bounds__(256, 2) void k_gemm_hmma(
    const __half* __restrict__ A, const __half* __restrict__ B,
    const float* __restrict__ bias, float* __restrict__ C,
    __half* __restrict__ Ch, int M, int N, int K) {
    extern __shared__ char smem[];
    const uint32_t sb = smem_u32(smem);
    const int tid = threadIdx.x;
    const int wid = tid >> 5, l = tid & 31;
    const int bm = blockIdx.y * 128;
    const int bn = blockIdx.x * 128;
    const int wm = (wid >> 2) * 64;
    const int wn = (wid & 3) * 32;

    float acc[4][4][4];
    #pragma unroll
    for (int a = 0; a < 4; a++)
        #pragma unroll
        for (int b = 0; b < 4; b++)
            #pragma unroll
            for (int c = 0; c < 4; c++) acc[a][b][c] = 0.f;

    const int NCH = K >> 6;                   // chunks of 64

    auto load_chunk = [&](int c, int buf) {
        const int k0 = c * 64;
        const uint32_t sbase = sb + buf * GT_BUF;
        #pragma unroll
        for (int j = 0; j < 8; j++) {
            int i = tid + j * 256;            // 0..2047
            int t = i >> 10;                  // 0 = A, 1 = B
            int idx = i & 1023;
            int row = idx >> 3, ch = idx & 7;
            uint32_t soff = row * 128 + ((ch ^ (row & 7)) << 4);
            const __half* src = (t ? B : A)
                + (size_t)((t ? bn : bm) + row) * K + k0 + ch * 8;
            CP_ASYNC16(sbase + t * GT_TILE + soff, src);
        }
    };

    auto compute = [&](int buf) {
        const uint32_t sbase = sb + buf * GT_BUF;
        #pragma unroll
        for (int ks = 0; ks < 4; ks++) {
            uint32_t ah[4][4], bh[4][2];
            const int ar_l = wm + ((l >> 3) & 1) * 8 + (l & 7);
            const int ach = 2 * ks + (l >> 4);
            #pragma unroll
            for (int mf = 0; mf < 4; mf++) {
                int r = ar_l + mf * 16;
                ldm_x4(ah[mf], sbase + r * 128 + ((ach ^ (r & 7)) << 4));
            }
            const int l16 = l & 15;
            const int br_l = wn + (l16 & 7);
            const int bch = 2 * ks + (l16 >> 3);
            #pragma unroll
            for (int nf = 0; nf < 4; nf++) {
                int r = br_l + nf * 8;
                ldm_x2(bh[nf], sbase + GT_TILE + r * 128 + ((bch ^ (r & 7)) << 4));
            }
            #pragma unroll
            for (int mf = 0; mf < 4; mf++)
                #pragma unroll
                for (int nf = 0; nf < 4; nf++)
                    mma_f16(acc[mf][nf], ah[mf], bh[nf]);
        }
    };

    load_chunk(0, 0);
    CP_COMMIT();
    load_chunk(1, 1);
    CP_COMMIT();
    for (int c = 0; c < NCH; c++) {
        CP_WAIT_GROUP(1);
        __syncthreads();
        if (c + 2 < NCH) load_chunk(c + 2, (c + 2) % 3);
        CP_COMMIT();
        compute(c % 3);
    }

    const int rbase = bm + wm + (l >> 2);
    const int cbase = bn + wn + (l & 3) * 2;
    #pragma unroll
    for (int mf = 0; mf < 4; mf++) {
        int r0 = rbase + mf * 16;
        #pragma unroll
        for (int nf = 0; nf < 4; nf++) {
            int cc = cbase + nf * 8;
            float2 bv = *(const float2*)&bias[cc];
            float v00 = acc[mf][nf][0] + bv.x, v01 = acc[mf][nf][1] + bv.y;
            float v10 = acc[mf][nf][2] + bv.x, v11 = acc[mf][nf][3] + bv.y;
            if (HALF_OUT) {
                *(uint32_t*)(Ch + (size_t)r0 * N + cc) = pack2(v00, v01);
                *(uint32_t*)(Ch + (size_t)(r0 + 8) * N + cc) = pack2(v10, v11);
            } else {
                *(float2*)&C[(size_t)r0 * N + cc] = make_float2(v00, v01);
                *(float2*)&C[(size_t)(r0 + 8) * N + cc] = make_float2(v10, v11);
            }
        }
    }
}

// ---------------- HMMA local attention (fp16) ----------------
// CTA = 128 q rows of one (b,h,group-half). 8 warps x 16 q rows.
// 3-stage KV ring (16 KB/stage: K 8K + V 8K), one barrier per 64-key chunk.
// smem: Q @ 0 (16 KB) | stage buf @ 16K + buf*16K. Total 64 KB -> 2 CTAs/SM.
#define AT_SMEM (16384 + 3 * 16384)

__global__ __launch_bounds__(256, 2) void k_attn_hmma(
    const __half* __restrict__ qg, __half* __restrict__ og) {
    extern __shared__ char smem[];
    const uint32_t sb = smem_u32(smem);
    const int half_ = blockIdx.x & 1, g = blockIdx.x >> 1;
    const int h = blockIdx.y, b = blockIdx.z;
    const int tid = threadIdx.x, wid = tid >> 5, l = tid & 31;
    const int qrow0 = b * SEQ + g * WIN + half_ * 128;
    const int wq = wid * 16;

    // ---- stage Q tile (128 rows x 128B), rides first commit group ----
    #pragma unroll
    for (int j = 0; j < 4; j++) {
        int idx = tid + j * 256;
        int row = idx >> 3, ch = idx & 7;
        const __half* src = qg + (size_t)(qrow0 + row) * QKVDIM + h * HDIM + ch * 8;
        CP_ASYNC16(sb + row * 128 + ((ch ^ (row & 7)) << 4), src);
    }

    auto stage_kv = [&](int c, int buf) {
        const int kr0 = b * SEQ + g * WIN - EXT + c * 64;
        const uint32_t base = sb + 16384 + buf * 16384;
        #pragma unroll
        for (int j = 0; j < 4; j++) {
            int i = tid + j * 256;
            int t = i >> 9;                   // 0 = K, 1 = V
            int idx = i & 511;
            int row = idx >> 3, ch = idx & 7;
            const __half* src = qg + (size_t)(kr0 + row) * QKVDIM
                + (t ? 2 * DIM : DIM) + h * HDIM + ch * 8;
            CP_ASYNC16(base + t * 8192 + row * 128 + ((ch ^ (row & 7)) << 4), src);
        }
    };

    uint32_t qf[4][4];
    float o[8][4];
    #pragma unroll
    for (int nf = 0; nf < 8; nf++)
        #pragma unroll
        for (int j = 0; j < 4; j++) o[nf][j] = 0.f;
    float ma = -1e30f, mb = -1e30f, la = 0.f, lb = 0.f;

    const int c0 = (g == 0) ? 2 : 0;
    const int c1 = (g == NGRP - 1) ? 6 : 8;
    const int nch = c1 - c0;

    stage_kv(c0, 0);
    CP_COMMIT();
    if (nch > 1) stage_kv(c0 + 1, 1);
    CP_COMMIT();

    for (int it = 0; it < nch; it++) {
        CP_WAIT_GROUP(1);
        __syncthreads();
        {
            int nxt = it + 2;
            if (nxt < nch) stage_kv(c0 + nxt, nxt % 3);
            CP_COMMIT();
        }
        if (it == 0) {
            #pragma unroll
            for (int ks = 0; ks < 4; ks++) {
                int r = wq + (l & 7) + ((l >> 3) & 1) * 8;
                int c = 2 * ks + ((l >> 4) & 1);
                ldm_x4(qf[ks], sb + r * 128 + ((c ^ (r & 7)) << 4));
            }
        }
        const uint32_t kb = sb + 16384 + (it % 3) * 16384;

        // ---- QK: S[16q x 64k] per warp ----
        float s[8][4];
        #pragma unroll
        for (int nf = 0; nf < 8; nf++)
            #pragma unroll
            for (int j = 0; j < 4; j++) s[nf][j] = 0.f;
        #pragma unroll
        for (int ks = 0; ks < 4; ks++) {
            const int r = (l & 7) + ((l >> 4) & 1) * 8;
            const int c = 2 * ks + ((l >> 3) & 1);
            #pragma unroll
            for (int np = 0; np < 4; np++) {
                int rr = np * 16 + r;
                uint32_t kf[4];
                ldm_x4(kf, kb + rr * 128 + ((c ^ (rr & 7)) << 4));
                mma_f16(s[2 * np],     qf[ks], kf);
                mma_f16(s[2 * np + 1], qf[ks], kf + 2);
            }
        }

        // ---- online softmax ----
        float mxa = -1e30f, mxb = -1e30f;
        #pragma unroll
        for (int nf = 0; nf < 8; nf++) {
            mxa = fmaxf(mxa, fmaxf(s[nf][0], s[nf][1]));
            mxb = fmaxf(mxb, fmaxf(s[nf][2], s[nf][3]));
        }
        mxa = fmaxf(mxa, __shfl_xor_sync(0xffffffffu, mxa, 1));
        mxa = fmaxf(mxa, __shfl_xor_sync(0xffffffffu, mxa, 2));
        mxb = fmaxf(mxb, __shfl_xor_sync(0xffffffffu, mxb, 1));
        mxb = fmaxf(mxb, __shfl_xor_sync(0xffffffffu, mxb, 2));
        float nma = fmaxf(ma, mxa), nmb = fmaxf(mb, mxb);
        float ca = __expf((ma - nma) * ATT_SCALE);
        float cb = __expf((mb - nmb) * ATT_SCALE);
        ma = nma; mb = nmb;
        la *= ca; lb *= cb;
        #pragma unroll
        for (int nf = 0; nf < 8; nf++) {
            s[nf][0] = __expf((s[nf][0] - ma) * ATT_SCALE);
            s[nf][1] = __expf((s[nf][1] - ma) * ATT_SCALE);
            s[nf][2] = __expf((s[nf][2] - mb) * ATT_SCALE);
            s[nf][3] = __expf((s[nf][3] - mb) * ATT_SCALE);
            la += s[nf][0] + s[nf][1];
            lb += s[nf][2] + s[nf][3];
            o[nf][0] *= ca; o[nf][1] *= ca;
            o[nf][2] *= cb; o[nf][3] *= cb;
        }

        // ---- pack P into A-frags ----
        uint32_t pf[4][4];
        #pragma unroll
        for (int j = 0; j < 4; j++) {
            pf[j][0] = pack2(s[2 * j][0],     s[2 * j][1]);
            pf[j][1] = pack2(s[2 * j][2],     s[2 * j][3]);
            pf[j][2] = pack2(s[2 * j + 1][0], s[2 * j + 1][1]);
            pf[j][3] = pack2(s[2 * j + 1][2], s[2 * j + 1][3]);
        }

        // ---- PV: O += P * V ----
        #pragma unroll
        for (int ks = 0; ks < 4; ks++) {
            const int r = ks * 16 + (l & 7) + ((l >> 3) & 1) * 8;
            const int c = (l >> 4) & 1;
            #pragma unroll
            for (int dp = 0; dp < 4; dp++) {
                int cc = 2 * dp + c;
                uint32_t vf[4];
                ldm_x4_t(vf, kb + 8192 + r * 128 + ((cc ^ (r & 7)) << 4));
                mma_f16(o[2 * dp],     pf[ks], vf);
                mma_f16(o[2 * dp + 1], pf[ks], vf + 2);
            }
        }
    }

    // ---- epilogue ----
    la += __shfl_xor_sync(0xffffffffu, la, 1);
    la += __shfl_xor_sync(0xffffffffu, la, 2);
    lb += __shfl_xor_sync(0xffffffffu, lb, 1);
    lb += __shfl_xor_sync(0xffffffffu, lb, 2);
    const float ia = 1.f / la, ib = 1.f / lb;
    const int ra = qrow0 + wq + (l >> 2);
    const int rb = ra + 8;
    const int colb = h * HDIM + 2 * (l & 3);
    #pragma unroll
    for (int nf = 0; nf < 8; nf++) {
        int cc = colb + nf * 8;
        *(uint32_t*)(og + (size_t)ra * DIM + cc) = pack2(o[nf][0] * ia, o[nf][1] * ia);
        *(uint32_t*)(og + (size_t)rb * DIM + cc) = pack2(o[nf][2] * ib, o[nf][3] * ib);
    }
}

// ---------------- launch ----------------
extern "C" void kernel_launch(void* const* d_in, const int* in_sizes, int n_in,
                              void* d_out, int out_size) {
    const float* x      = (const float*)d_in[0];
    const float* w_qkv  = (const float*)d_in[1];
    const float* b_qkv  = (const float*)d_in[2];
    const float* w_proj = (const float*)d_in[3];
    const float* b_proj = (const float*)d_in[4];
    float* out = (float*)d_out;

    __half *qh, *xh, *wqh, *ah, *wph;
    cudaGetSymbolAddress((void**)&qh,  g_qkvh);
    cudaGetSymbolAddress((void**)&xh,  g_xh);
    cudaGetSymbolAddress((void**)&wqh, g_wqkvh);
    cudaGetSymbolAddress((void**)&ah,  g_attnh);
    cudaGetSymbolAddress((void**)&wph, g_wprojh);

    cudaFuncSetAttribute(k_gemm_hmma<true>,  cudaFuncAttributeMaxDynamicSharedMemorySize, GT_TOTAL);
    cudaFuncSetAttribute(k_gemm_hmma<false>, cudaFuncAttributeMaxDynamicSharedMemorySize, GT_TOTAL);
    cudaFuncSetAttribute(k_attn_hmma, cudaFuncAttributeMaxDynamicSharedMemorySize, AT_SMEM);

    // 1. fp32 -> fp16 converts
    k_cvt<<<(MROWS * DIM / 4 + 255) / 256, 256>>>(x, xh, MROWS * DIM / 4);
    k_cvt<<<(QKVDIM * DIM / 4 + 255) / 256, 256>>>(w_qkv, wqh, QKVDIM * DIM / 4);
    k_cvt<<<(DIM * DIM / 4 + 255) / 256, 256>>>(w_proj, wph, DIM * DIM / 4);

    // 2. QKV projection -> fp16
    k_gemm_hmma<true><<<dim3(QKVDIM / 128, MROWS / 128), 256, GT_TOTAL>>>(
        xh, wqh, b_qkv, nullptr, qh, MROWS, QKVDIM, DIM);

    // 3. local windowed attention -> fp16
    k_attn_hmma<<<dim3(NGRP * 2, NHEAD, BATCH), 256, AT_SMEM>>>(qh, ah);

    // 4. output projection -> fp32 out
    k_gemm_hmma<false><<<dim3(DIM / 128, MROWS / 128), 256, GT_TOTAL>>>(
        ah, wph, b_proj, out, nullptr, MROWS, DIM, DIM);
}